// round 1
// baseline (speedup 1.0000x reference)
#include <cuda_runtime.h>
#include <math.h>

#define EPSBN 1e-5f

// Problem constants: B=4, C=2048, R=512, H=W=64, N=4096
#define BATCH 4
#define CDIM  2048
#define RDIM  512
#define NDIM  4096

// Scratch: __device__ globals (no allocation allowed in kernel_launch)
__device__ float g_f  [(size_t)BATCH * RDIM * NDIM];   // 33.5 MB
__device__ float g_q  [(size_t)BATCH * RDIM * NDIM];
__device__ float g_k  [(size_t)BATCH * RDIM * NDIM];
__device__ float g_v  [(size_t)BATCH * RDIM * NDIM];
__device__ float g_upd[(size_t)BATCH * RDIM * NDIM];
__device__ float g_attn[(size_t)BATCH * NDIM * NDIM];  // 268 MB

// ---------------------------------------------------------------------------
// Generic 128x128x8 fp32 tiled GEMM, 256 threads, 8x8 per thread.
//   C[m,n] (+batch) = sum_k A[m,k] * (B[k,n] (+ B2[k,n]))
//   A element: A[m*sAm + k*sAk]; B element: B[k*sBk + n*sBn]
//   A_KC : A is k-contiguous (sAk==1)  -> vector-load along k, transpose in smem
//   B_NC : B is n-contiguous (sBn==1)  -> vector-load along n directly
//   EPI  : apply y = relu(acc*inv[m] + (b[m]-mean[m]*inv[m])), inv=g/sqrt(v+eps)
//   HASB2: B-operand is elementwise sum of two tensors (same strides)
// All dims: M,N multiples of 128; K multiple of 8. No bounds checks.
// ---------------------------------------------------------------------------
template<bool A_KC, bool B_NC, bool EPI, bool HASB2>
__global__ __launch_bounds__(256) void gemm_kernel(
    int K,
    const float* __restrict__ A, int sAm, int sAk, size_t aBatch,
    const float* __restrict__ B, int sBk, int sBn, size_t bBatch,
    const float* __restrict__ B2, size_t b2Batch,
    float* __restrict__ C, int ldc, size_t cBatch,
    const float* __restrict__ gg, const float* __restrict__ bb,
    const float* __restrict__ mm, const float* __restrict__ vv)
{
    __shared__ float As[8][128];
    __shared__ float Bs[8][128];

    const int tid = threadIdx.x;
    const int bm = blockIdx.y * 128;
    const int bn = blockIdx.x * 128;
    const int bz = blockIdx.z;

    A += (size_t)bz * aBatch;
    B += (size_t)bz * bBatch;
    C += (size_t)bz * cBatch;
    const float* Bq = HASB2 ? (B2 + (size_t)bz * b2Batch) : nullptr;

    float acc[8][8];
    #pragma unroll
    for (int i = 0; i < 8; i++)
        #pragma unroll
        for (int j = 0; j < 8; j++)
            acc[i][j] = 0.0f;

    const int tx = tid & 15;   // n micro-tile
    const int ty = tid >> 4;   // m micro-tile

    for (int k0 = 0; k0 < K; k0 += 8) {
        // ---- load A tile (8 x 128, stored As[k][m]) ----
        if (A_KC) {
            // k-contiguous: float4 along k, scatter-transpose into smem
            const int m  = tid >> 1;
            const int kq = (tid & 1) * 4;
            const float4 t = *reinterpret_cast<const float4*>(
                A + (size_t)(bm + m) * sAm + (k0 + kq));
            As[kq + 0][m] = t.x; As[kq + 1][m] = t.y;
            As[kq + 2][m] = t.z; As[kq + 3][m] = t.w;
        } else {
            // m-contiguous: float4 along m, direct store
            const int kk = tid >> 5;
            const int m  = (tid & 31) * 4;
            *reinterpret_cast<float4*>(&As[kk][m]) =
                *reinterpret_cast<const float4*>(
                    A + (size_t)(k0 + kk) * sAk + (bm + m));
        }
        // ---- load B tile (8 x 128, stored Bs[k][n]) ----
        if (B_NC) {
            const int kk = tid >> 5;
            const int n  = (tid & 31) * 4;
            float4 t = *reinterpret_cast<const float4*>(
                B + (size_t)(k0 + kk) * sBk + (bn + n));
            if (HASB2) {
                const float4 u = *reinterpret_cast<const float4*>(
                    Bq + (size_t)(k0 + kk) * sBk + (bn + n));
                t.x += u.x; t.y += u.y; t.z += u.z; t.w += u.w;
            }
            *reinterpret_cast<float4*>(&Bs[kk][n]) = t;
        } else {
            // k-contiguous B (attn^T case): float4 along k, scatter-transpose
            const int n  = tid >> 1;
            const int kq = (tid & 1) * 4;
            const float4 t = *reinterpret_cast<const float4*>(
                B + (size_t)(bn + n) * sBn + (k0 + kq));
            Bs[kq + 0][n] = t.x; Bs[kq + 1][n] = t.y;
            Bs[kq + 2][n] = t.z; Bs[kq + 3][n] = t.w;
        }
        __syncthreads();

        #pragma unroll
        for (int kk = 0; kk < 8; kk++) {
            float a[8], bv[8];
            *reinterpret_cast<float4*>(a)      = *reinterpret_cast<const float4*>(&As[kk][ty * 8]);
            *reinterpret_cast<float4*>(a + 4)  = *reinterpret_cast<const float4*>(&As[kk][ty * 8 + 4]);
            *reinterpret_cast<float4*>(bv)     = *reinterpret_cast<const float4*>(&Bs[kk][tx * 8]);
            *reinterpret_cast<float4*>(bv + 4) = *reinterpret_cast<const float4*>(&Bs[kk][tx * 8 + 4]);
            #pragma unroll
            for (int i = 0; i < 8; i++)
                #pragma unroll
                for (int j = 0; j < 8; j++)
                    acc[i][j] = fmaf(a[i], bv[j], acc[i][j]);
        }
        __syncthreads();
    }

    // ---- epilogue ----
    #pragma unroll
    for (int i = 0; i < 8; i++) {
        const int o = bm + ty * 8 + i;
        float sc = 1.0f, be = 0.0f;
        if (EPI) {
            const float inv = gg[o] * rsqrtf(vv[o] + EPSBN);
            sc = inv;
            be = bb[o] - mm[o] * inv;
        }
        float* cp = C + (size_t)o * ldc + bn + tx * 8;
        float4 r0, r1;
        if (EPI) {
            r0.x = fmaxf(acc[i][0] * sc + be, 0.0f);
            r0.y = fmaxf(acc[i][1] * sc + be, 0.0f);
            r0.z = fmaxf(acc[i][2] * sc + be, 0.0f);
            r0.w = fmaxf(acc[i][3] * sc + be, 0.0f);
            r1.x = fmaxf(acc[i][4] * sc + be, 0.0f);
            r1.y = fmaxf(acc[i][5] * sc + be, 0.0f);
            r1.z = fmaxf(acc[i][6] * sc + be, 0.0f);
            r1.w = fmaxf(acc[i][7] * sc + be, 0.0f);
        } else {
            r0.x = acc[i][0]; r0.y = acc[i][1]; r0.z = acc[i][2]; r0.w = acc[i][3];
            r1.x = acc[i][4]; r1.y = acc[i][5]; r1.z = acc[i][6]; r1.w = acc[i][7];
        }
        *reinterpret_cast<float4*>(cp)     = r0;
        *reinterpret_cast<float4*>(cp + 4) = r1;
    }
}

// ---------------------------------------------------------------------------
// In-place row softmax, row length 4096, one block per row, 256 threads.
// Row kept in registers (16 floats/thread).
// ---------------------------------------------------------------------------
__global__ __launch_bounds__(256) void softmax_kernel(float* __restrict__ attn)
{
    float* row = attn + (size_t)blockIdx.x * NDIM;
    const int t = threadIdx.x;

    float4 v[4];
    float mx = -3.4e38f;
    #pragma unroll
    for (int i = 0; i < 4; i++) {
        v[i] = reinterpret_cast<const float4*>(row)[i * 256 + t];
        mx = fmaxf(mx, fmaxf(fmaxf(v[i].x, v[i].y), fmaxf(v[i].z, v[i].w)));
    }

    __shared__ float red_m[8];
    __shared__ float red_s[8];
    #pragma unroll
    for (int o = 16; o > 0; o >>= 1)
        mx = fmaxf(mx, __shfl_xor_sync(0xffffffffu, mx, o));
    if ((t & 31) == 0) red_m[t >> 5] = mx;
    __syncthreads();
    mx = fmaxf(fmaxf(fmaxf(red_m[0], red_m[1]), fmaxf(red_m[2], red_m[3])),
               fmaxf(fmaxf(red_m[4], red_m[5]), fmaxf(red_m[6], red_m[7])));

    float sum = 0.0f;
    #pragma unroll
    for (int i = 0; i < 4; i++) {
        v[i].x = expf(v[i].x - mx); sum += v[i].x;
        v[i].y = expf(v[i].y - mx); sum += v[i].y;
        v[i].z = expf(v[i].z - mx); sum += v[i].z;
        v[i].w = expf(v[i].w - mx); sum += v[i].w;
    }
    #pragma unroll
    for (int o = 16; o > 0; o >>= 1)
        sum += __shfl_xor_sync(0xffffffffu, sum, o);
    if ((t & 31) == 0) red_s[t >> 5] = sum;
    __syncthreads();
    sum = (red_s[0] + red_s[1]) + (red_s[2] + red_s[3])
        + (red_s[4] + red_s[5]) + (red_s[6] + red_s[7]);

    const float r = 1.0f / sum;
    #pragma unroll
    for (int i = 0; i < 4; i++) {
        v[i].x *= r; v[i].y *= r; v[i].z *= r; v[i].w *= r;
        reinterpret_cast<float4*>(row)[i * 256 + t] = v[i];
    }
}

// ---------------------------------------------------------------------------
extern "C" void kernel_launch(void* const* d_in, const int* in_sizes, int n_in,
                              void* d_out, int out_size)
{
    (void)in_sizes; (void)n_in; (void)out_size;

    const float* feature = (const float*)d_in[0];
    const float* rW = (const float*)d_in[1];
    const float* rg = (const float*)d_in[2];
    const float* rb = (const float*)d_in[3];
    const float* rm = (const float*)d_in[4];
    const float* rv = (const float*)d_in[5];
    const float* qW = (const float*)d_in[6];
    const float* qg = (const float*)d_in[7];
    const float* qb = (const float*)d_in[8];
    const float* qm = (const float*)d_in[9];
    const float* qv = (const float*)d_in[10];
    const float* kW = (const float*)d_in[11];
    const float* kg = (const float*)d_in[12];
    const float* kb = (const float*)d_in[13];
    const float* km = (const float*)d_in[14];
    const float* kv = (const float*)d_in[15];
    const float* vW = (const float*)d_in[16];
    const float* vg = (const float*)d_in[17];
    const float* vb = (const float*)d_in[18];
    const float* vm = (const float*)d_in[19];
    const float* vv = (const float*)d_in[20];
    const float* uW = (const float*)d_in[21];
    const float* ug = (const float*)d_in[22];
    const float* ub = (const float*)d_in[23];
    const float* um = (const float*)d_in[24];
    const float* uv = (const float*)d_in[25];

    float *f, *q, *k, *v, *upd, *attn;
    cudaGetSymbolAddress((void**)&f,    g_f);
    cudaGetSymbolAddress((void**)&q,    g_q);
    cudaGetSymbolAddress((void**)&k,    g_k);
    cudaGetSymbolAddress((void**)&v,    g_v);
    cudaGetSymbolAddress((void**)&upd,  g_upd);
    cudaGetSymbolAddress((void**)&attn, g_attn);

    const size_t fB = (size_t)RDIM * NDIM;      // per-batch activation stride [R,N]
    const size_t xB = (size_t)CDIM * NDIM;      // per-batch feature stride [C,N]
    const size_t aB = (size_t)NDIM * NDIM;      // per-batch attn stride

    // 1) f = CBR(feature, r): [R,C]x[C,N]
    gemm_kernel<true, true, true, false><<<dim3(NDIM/128, RDIM/128, BATCH), 256>>>(
        CDIM,
        rW, CDIM, 1, 0,
        feature, NDIM, 1, xB,
        nullptr, 0,
        f, NDIM, fB,
        rg, rb, rm, rv);

    // 2) q, k, v = CBR(f, {q,k,v}): [R,R]x[R,N]
    gemm_kernel<true, true, true, false><<<dim3(NDIM/128, RDIM/128, BATCH), 256>>>(
        RDIM, qW, RDIM, 1, 0, f, NDIM, 1, fB, nullptr, 0, q, NDIM, fB, qg, qb, qm, qv);
    gemm_kernel<true, true, true, false><<<dim3(NDIM/128, RDIM/128, BATCH), 256>>>(
        RDIM, kW, RDIM, 1, 0, f, NDIM, 1, fB, nullptr, 0, k, NDIM, fB, kg, kb, km, kv);
    gemm_kernel<true, true, true, false><<<dim3(NDIM/128, RDIM/128, BATCH), 256>>>(
        RDIM, vW, RDIM, 1, 0, f, NDIM, 1, fB, nullptr, 0, v, NDIM, fB, vg, vb, vm, vv);

    // 3) logits[n,m] = sum_c q[c,n]*k[c,m]  (Q^T K, "TN")
    gemm_kernel<false, true, false, false><<<dim3(NDIM/128, NDIM/128, BATCH), 256>>>(
        RDIM,
        q, 1, NDIM, fB,
        k, NDIM, 1, fB,
        nullptr, 0,
        attn, NDIM, aB,
        nullptr, nullptr, nullptr, nullptr);

    // 4) softmax over last dim, in place
    softmax_kernel<<<BATCH * NDIM, 256>>>(attn);

    // 5) upd[c,n] = sum_m v[c,m] * attn[n,m]  (V * P^T, "NT")
    gemm_kernel<true, false, false, false><<<dim3(NDIM/128, RDIM/128, BATCH), 256>>>(
        NDIM,
        v, NDIM, 1, fB,
        attn, 1, NDIM, aB,
        nullptr, 0,
        upd, NDIM, fB,
        nullptr, nullptr, nullptr, nullptr);

    // 6) out = CBR(f + upd, u): [C,R]x[R,N]
    gemm_kernel<true, true, true, true><<<dim3(NDIM/128, CDIM/128, BATCH), 256>>>(
        RDIM,
        uW, RDIM, 1, 0,
        f, NDIM, 1, fB,
        upd, fB,
        (float*)d_out, NDIM, xB,
        ug, ub, um, uv);
}

// round 3
// speedup vs baseline: 2.2596x; 2.2596x over previous
#include <cuda_runtime.h>
#include <cuda_bf16.h>
#include <stdint.h>
#include <math.h>

#define BATCH 4
#define CDIM  2048
#define RDIM  512
#define NDIM  4096
#define EPSBN 1e-5f

typedef __nv_bfloat16 bf16;

// ===========================================================================
// Scratch (device globals; no allocation allowed)
// ===========================================================================
__device__ bf16 g_XTh[(size_t)BATCH * NDIM * CDIM];   // feature^T hi  [B][N][C]
__device__ bf16 g_XTl[(size_t)BATCH * NDIM * CDIM];
__device__ bf16 g_fTh[(size_t)BATCH * NDIM * RDIM];   // f^T [B][N][R]
__device__ bf16 g_fTl[(size_t)BATCH * NDIM * RDIM];
__device__ bf16 g_qTh[(size_t)BATCH * NDIM * RDIM];
__device__ bf16 g_qTl[(size_t)BATCH * NDIM * RDIM];
__device__ bf16 g_kTh[(size_t)BATCH * NDIM * RDIM];
__device__ bf16 g_kTl[(size_t)BATCH * NDIM * RDIM];
__device__ bf16 g_vh [(size_t)BATCH * RDIM * NDIM];   // v [B][R][N]
__device__ bf16 g_vl [(size_t)BATCH * RDIM * NDIM];
__device__ float g_logits[(size_t)BATCH * NDIM * NDIM];
__device__ bf16 g_Ph [(size_t)BATCH * NDIM * NDIM];
__device__ bf16 g_Pl [(size_t)BATCH * NDIM * NDIM];
__device__ bf16 g_resh[(size_t)BATCH * NDIM * RDIM];  // (f+upd)^T [B][N][R]
__device__ bf16 g_resl[(size_t)BATCH * NDIM * RDIM];
__device__ bf16 g_rWh[RDIM * CDIM], g_rWl[RDIM * CDIM];
__device__ bf16 g_qWh[RDIM * RDIM], g_qWl[RDIM * RDIM];
__device__ bf16 g_kWh[RDIM * RDIM], g_kWl[RDIM * RDIM];
__device__ bf16 g_vWh[RDIM * RDIM], g_vWl[RDIM * RDIM];
__device__ bf16 g_uWh[CDIM * RDIM], g_uWl[CDIM * RDIM];

// ===========================================================================
// Helpers (non-'a' instructions only: ldmatrix, mma.sync, cp.async)
// ===========================================================================
__device__ __forceinline__ uint32_t smem_u32(const void* p) {
    uint32_t a;
    asm("{ .reg .u64 t; cvta.to.shared.u64 t, %1; cvt.u32.u64 %0, t; }" : "=r"(a) : "l"(p));
    return a;
}
__device__ __forceinline__ void ldm_x4(uint32_t* r, uint32_t addr) {
    asm volatile("ldmatrix.sync.aligned.m8n8.x4.shared.b16 {%0,%1,%2,%3}, [%4];"
                 : "=r"(r[0]), "=r"(r[1]), "=r"(r[2]), "=r"(r[3]) : "r"(addr));
}
__device__ __forceinline__ void mma_bf16(float* d, const uint32_t* a, const uint32_t* b) {
    asm volatile("mma.sync.aligned.m16n8k16.row.col.f32.bf16.bf16.f32 "
                 "{%0,%1,%2,%3}, {%4,%5,%6,%7}, {%8,%9}, {%0,%1,%2,%3};"
                 : "+f"(d[0]), "+f"(d[1]), "+f"(d[2]), "+f"(d[3])
                 : "r"(a[0]), "r"(a[1]), "r"(a[2]), "r"(a[3]), "r"(b[0]), "r"(b[1]));
}
__device__ __forceinline__ void cp_async16(uint32_t dst, const void* src) {
    asm volatile("cp.async.cg.shared.global [%0], [%1], 16;" :: "r"(dst), "l"(src) : "memory");
}
#define CP_COMMIT() asm volatile("cp.async.commit_group;" ::: "memory")
#define CP_WAIT(n)  asm volatile("cp.async.wait_group %0;" :: "n"(n) : "memory")

// ===========================================================================
// Prep kernels
// ===========================================================================
__global__ void split_w_kernel(const float* __restrict__ w, bf16* __restrict__ h,
                               bf16* __restrict__ l, int n) {
    int i = blockIdx.x * 256 + threadIdx.x;
    if (i < n) {
        float x = w[i];
        bf16 hi = __float2bfloat16(x);
        h[i] = hi;
        l[i] = __float2bfloat16(x - __bfloat162float(hi));
    }
}

// feature [B][C][N] fp32 -> XT [B][N][C] split bf16
__global__ __launch_bounds__(256) void transpose_split_kernel(
    const float* __restrict__ src, bf16* __restrict__ dh, bf16* __restrict__ dl) {
    __shared__ float t[32][33];
    const int bz = blockIdx.z;
    const float* s = src + (size_t)bz * CDIM * NDIM;
    const size_t dbase = (size_t)bz * NDIM * CDIM;
    const int c0 = blockIdx.x * 32, n0 = blockIdx.y * 32;
    const int tx = threadIdx.x, ty = threadIdx.y;  // 32 x 8
    #pragma unroll
    for (int i = 0; i < 4; i++)
        t[ty + 8 * i][tx] = s[(size_t)(c0 + ty + 8 * i) * NDIM + n0 + tx];
    __syncthreads();
    #pragma unroll
    for (int i = 0; i < 4; i++) {
        const int n = n0 + ty + 8 * i, c = c0 + tx;
        const float x = t[tx][ty + 8 * i];
        bf16 h = __float2bfloat16(x);
        dh[dbase + (size_t)n * CDIM + c] = h;
        dl[dbase + (size_t)n * CDIM + c] = __float2bfloat16(x - __bfloat162float(h));
    }
}

// ===========================================================================
// Split-bf16 mma.sync GEMM: D[m,n] = sum_k A[m,k]*B[n,k] (both K-major).
// CTA tile 128x128, BK=32, 256 thr (8 warps, each 32m x 64n), double-buffered
// cp.async. SMEM rows padded to 40 bf16 (80B) -> conflict-free ldmatrix.
// ===========================================================================
enum { EPI_BNCOL_SPLIT = 0, EPI_BNROW_SPLIT = 1, EPI_F32 = 2,
       EPI_RESID_SPLIT = 3, EPI_BNROW_F32 = 4 };

#define LDT_B    80        // smem row stride bytes (40 bf16)
#define MAT_SZ   10240     // 128 rows * 80 B
#define BUF_SZ   40960     // Ah, Al, Bh, Bl
#define SMEM_HDR 1024
#define SMEM_TOTAL (SMEM_HDR + 2 * BUF_SZ)   // 82944

template<int EPI>
__global__ __launch_bounds__(256, 1) void mma_gemm(
    int K,
    const bf16* __restrict__ Ah, const bf16* __restrict__ Al, long lda, size_t aB,
    const bf16* __restrict__ Bh, const bf16* __restrict__ Bl, long ldb, size_t bB,
    void* __restrict__ O1, void* __restrict__ O2, long ldc, size_t cB,
    const float* __restrict__ bn_g, const float* __restrict__ bn_b,
    const float* __restrict__ bn_m, const float* __restrict__ bn_v,
    const bf16* __restrict__ Rh, const bf16* __restrict__ Rl, long ldr, size_t rB)
{
    extern __shared__ __align__(128) char smem[];
    const uint32_t sb = smem_u32(smem);
    const int tid  = threadIdx.x;
    const int wid  = tid >> 5;
    const int lane = tid & 31;
    const int bm = blockIdx.y * 128;
    const int bn = blockIdx.x * 128;
    const int bz = blockIdx.z;

    const bf16* pAh = Ah + (size_t)bz * aB;
    const bf16* pAl = Al + (size_t)bz * aB;
    const bf16* pBh = Bh + (size_t)bz * bB;
    const bf16* pBl = Bl + (size_t)bz * bB;

    float* sinv  = (float*)(smem);
    float* sbeta = (float*)(smem + 512);
    if ((EPI == EPI_BNCOL_SPLIT || EPI == EPI_BNROW_SPLIT || EPI == EPI_BNROW_F32)
        && tid < 128) {
        const int idx = (EPI == EPI_BNCOL_SPLIT) ? (bn + tid) : (bm + tid);
        const float iv = bn_g[idx] * rsqrtf(bn_v[idx] + EPSBN);
        sinv[tid]  = iv;
        sbeta[tid] = bn_b[idx] - bn_m[idx] * iv;
    }

    // per-thread cp.async mapping: 8 chunks of 16B
    // i = t*256+tid; matrix = i>>9 (0..3), w = i&511; row = w>>2; j = w&3
    const int iters = K >> 5;

    auto load_tiles = [&](int it) {
        const int k0 = it << 5;
        const uint32_t base = sb + SMEM_HDR + (it & 1) * BUF_SZ;
        #pragma unroll
        for (int t = 0; t < 8; t++) {
            const int i = t * 256 + tid;
            const int mat = i >> 9;
            const int w = i & 511;
            const int row = w >> 2, j = w & 3;
            const uint32_t dst = base + mat * MAT_SZ + row * LDT_B + j * 16;
            const bf16* src;
            if      (mat == 0) src = pAh + (size_t)(bm + row) * lda + k0 + j * 8;
            else if (mat == 1) src = pAl + (size_t)(bm + row) * lda + k0 + j * 8;
            else if (mat == 2) src = pBh + (size_t)(bn + row) * ldb + k0 + j * 8;
            else               src = pBl + (size_t)(bn + row) * ldb + k0 + j * 8;
            cp_async16(dst, src);
        }
        CP_COMMIT();
    };

    float acc[2][8][4];
    #pragma unroll
    for (int mi = 0; mi < 2; mi++)
        #pragma unroll
        for (int ni = 0; ni < 8; ni++)
            #pragma unroll
            for (int j = 0; j < 4; j++) acc[mi][ni][j] = 0.0f;

    const int warp_m = wid & 3;      // 4 warps along m (32 rows each)
    const int warp_n = wid >> 2;     // 2 warps along n (64 cols each)

    // ldmatrix lane address components
    const uint32_t aLane = (uint32_t)((warp_m * 32 + (lane & 15)) * LDT_B + (lane >> 4) * 16);
    const uint32_t bLane = (uint32_t)((warp_n * 64 + (lane & 7) + ((lane & 16) >> 1)) * LDT_B
                                      + (lane & 8) * 2);

    load_tiles(0);

    for (int it = 0; it < iters; ++it) {
        if (it + 1 < iters) { load_tiles(it + 1); CP_WAIT(1); }
        else                { CP_WAIT(0); }
        __syncthreads();

        const uint32_t base = sb + SMEM_HDR + (it & 1) * BUF_SZ;
        #pragma unroll
        for (int ks = 0; ks < 2; ks++) {
            uint32_t ah[2][4], al[2][4], bh[8][2], bl[8][2];
            #pragma unroll
            for (int mi = 0; mi < 2; mi++) {
                const uint32_t ad = base + aLane + mi * (16 * LDT_B) + ks * 32;
                ldm_x4(ah[mi], ad);
                ldm_x4(al[mi], ad + MAT_SZ);
            }
            #pragma unroll
            for (int nf = 0; nf < 4; nf++) {
                const uint32_t bd = base + 2 * MAT_SZ + bLane + nf * (16 * LDT_B) + ks * 32;
                uint32_t r[4];
                ldm_x4(r, bd);
                bh[2 * nf][0] = r[0]; bh[2 * nf][1] = r[1];
                bh[2 * nf + 1][0] = r[2]; bh[2 * nf + 1][1] = r[3];
                ldm_x4(r, bd + MAT_SZ);
                bl[2 * nf][0] = r[0]; bl[2 * nf][1] = r[1];
                bl[2 * nf + 1][0] = r[2]; bl[2 * nf + 1][1] = r[3];
            }
            #pragma unroll
            for (int mi = 0; mi < 2; mi++)
                #pragma unroll
                for (int ni = 0; ni < 8; ni++) {
                    mma_bf16(acc[mi][ni], ah[mi], bh[ni]);
                    mma_bf16(acc[mi][ni], ah[mi], bl[ni]);
                    mma_bf16(acc[mi][ni], al[mi], bh[ni]);
                }
        }
        __syncthreads();
    }

    // ---------------- epilogue (register accumulators) ----------------
    const int r_lo = lane >> 2;          // 0..7
    const int c_lo = (lane & 3) * 2;     // 0,2,4,6
    #pragma unroll
    for (int mi = 0; mi < 2; mi++) {
        #pragma unroll
        for (int half = 0; half < 2; half++) {   // d0,d1 vs d2,d3
            const int lrow = warp_m * 32 + mi * 16 + r_lo + half * 8;
            const int grow = bm + lrow;
            #pragma unroll
            for (int ni = 0; ni < 8; ni++) {
                const int lcol = warp_n * 64 + ni * 8 + c_lo;
                const int gcol = bn + lcol;
                float v0 = acc[mi][ni][half * 2 + 0];
                float v1 = acc[mi][ni][half * 2 + 1];

                if (EPI == EPI_BNCOL_SPLIT) {
                    v0 = fmaxf(v0 * sinv[lcol]     + sbeta[lcol],     0.0f);
                    v1 = fmaxf(v1 * sinv[lcol + 1] + sbeta[lcol + 1], 0.0f);
                } else if (EPI == EPI_BNROW_SPLIT || EPI == EPI_BNROW_F32) {
                    v0 = fmaxf(v0 * sinv[lrow] + sbeta[lrow], 0.0f);
                    v1 = fmaxf(v1 * sinv[lrow] + sbeta[lrow], 0.0f);
                } else if (EPI == EPI_RESID_SPLIT) {
                    const size_t ro = (size_t)bz * rB + (size_t)grow * ldr + gcol;
                    const __nv_bfloat162 rh = *(const __nv_bfloat162*)(Rh + ro);
                    const __nv_bfloat162 rl = *(const __nv_bfloat162*)(Rl + ro);
                    v0 += __bfloat162float(rh.x) + __bfloat162float(rl.x);
                    v1 += __bfloat162float(rh.y) + __bfloat162float(rl.y);
                }

                if (EPI == EPI_F32 || EPI == EPI_BNROW_F32) {
                    float* po = (float*)O1 + (size_t)bz * cB + (size_t)grow * ldc + gcol;
                    po[0] = v0; po[1] = v1;
                } else {
                    const size_t oo = (size_t)bz * cB + (size_t)grow * ldc + gcol;
                    bf16 h0 = __float2bfloat16(v0);
                    bf16 h1 = __float2bfloat16(v1);
                    __nv_bfloat162 hv; hv.x = h0; hv.y = h1;
                    __nv_bfloat162 lv;
                    lv.x = __float2bfloat16(v0 - __bfloat162float(h0));
                    lv.y = __float2bfloat16(v1 - __bfloat162float(h1));
                    *(__nv_bfloat162*)((bf16*)O1 + oo) = hv;
                    *(__nv_bfloat162*)((bf16*)O2 + oo) = lv;
                }
            }
        }
    }
}

// ===========================================================================
// Row softmax over fp32 logits -> split bf16 P
// ===========================================================================
__global__ __launch_bounds__(256) void softmax_split_kernel(
    const float* __restrict__ logits, bf16* __restrict__ ph, bf16* __restrict__ pl)
{
    const float* row = logits + (size_t)blockIdx.x * NDIM;
    __nv_bfloat162* ph2 = (__nv_bfloat162*)(ph + (size_t)blockIdx.x * NDIM);
    __nv_bfloat162* pl2 = (__nv_bfloat162*)(pl + (size_t)blockIdx.x * NDIM);
    const int t = threadIdx.x;

    float4 v[4];
    float mx = -3.4e38f;
    #pragma unroll
    for (int i = 0; i < 4; i++) {
        v[i] = reinterpret_cast<const float4*>(row)[i * 256 + t];
        mx = fmaxf(mx, fmaxf(fmaxf(v[i].x, v[i].y), fmaxf(v[i].z, v[i].w)));
    }
    __shared__ float red_m[8], red_s[8];
    #pragma unroll
    for (int o = 16; o > 0; o >>= 1) mx = fmaxf(mx, __shfl_xor_sync(0xffffffffu, mx, o));
    if ((t & 31) == 0) red_m[t >> 5] = mx;
    __syncthreads();
    mx = fmaxf(fmaxf(fmaxf(red_m[0], red_m[1]), fmaxf(red_m[2], red_m[3])),
               fmaxf(fmaxf(red_m[4], red_m[5]), fmaxf(red_m[6], red_m[7])));
    float sum = 0.0f;
    #pragma unroll
    for (int i = 0; i < 4; i++) {
        v[i].x = expf(v[i].x - mx); sum += v[i].x;
        v[i].y = expf(v[i].y - mx); sum += v[i].y;
        v[i].z = expf(v[i].z - mx); sum += v[i].z;
        v[i].w = expf(v[i].w - mx); sum += v[i].w;
    }
    #pragma unroll
    for (int o = 16; o > 0; o >>= 1) sum += __shfl_xor_sync(0xffffffffu, sum, o);
    if ((t & 31) == 0) red_s[t >> 5] = sum;
    __syncthreads();
    sum = (red_s[0] + red_s[1]) + (red_s[2] + red_s[3])
        + (red_s[4] + red_s[5]) + (red_s[6] + red_s[7]);
    const float r = 1.0f / sum;
    #pragma unroll
    for (int i = 0; i < 4; i++) {
        float a = v[i].x * r, b = v[i].y * r, c = v[i].z * r, d = v[i].w * r;
        bf16 ha = __float2bfloat16(a), hb = __float2bfloat16(b);
        bf16 hc = __float2bfloat16(c), hd = __float2bfloat16(d);
        __nv_bfloat162 h0; h0.x = ha; h0.y = hb;
        __nv_bfloat162 h1; h1.x = hc; h1.y = hd;
        ph2[(i * 256 + t) * 2 + 0] = h0;
        ph2[(i * 256 + t) * 2 + 1] = h1;
        __nv_bfloat162 l0, l1;
        l0.x = __float2bfloat16(a - __bfloat162float(ha));
        l0.y = __float2bfloat16(b - __bfloat162float(hb));
        l1.x = __float2bfloat16(c - __bfloat162float(hc));
        l1.y = __float2bfloat16(d - __bfloat162float(hd));
        pl2[(i * 256 + t) * 2 + 0] = l0;
        pl2[(i * 256 + t) * 2 + 1] = l1;
    }
}

// ===========================================================================
extern "C" void kernel_launch(void* const* d_in, const int* in_sizes, int n_in,
                              void* d_out, int out_size)
{
    (void)in_sizes; (void)n_in; (void)out_size;
    const float* feature = (const float*)d_in[0];
    const float* rW = (const float*)d_in[1];
    const float* rg = (const float*)d_in[2];  const float* rb = (const float*)d_in[3];
    const float* rm = (const float*)d_in[4];  const float* rv = (const float*)d_in[5];
    const float* qW = (const float*)d_in[6];
    const float* qg = (const float*)d_in[7];  const float* qb = (const float*)d_in[8];
    const float* qm = (const float*)d_in[9];  const float* qv = (const float*)d_in[10];
    const float* kW = (const float*)d_in[11];
    const float* kg = (const float*)d_in[12]; const float* kb = (const float*)d_in[13];
    const float* km = (const float*)d_in[14]; const float* kv = (const float*)d_in[15];
    const float* vW = (const float*)d_in[16];
    const float* vg = (const float*)d_in[17]; const float* vb = (const float*)d_in[18];
    const float* vm = (const float*)d_in[19]; const float* vv = (const float*)d_in[20];
    const float* uW = (const float*)d_in[21];
    const float* ug = (const float*)d_in[22]; const float* ub = (const float*)d_in[23];
    const float* um = (const float*)d_in[24]; const float* uv = (const float*)d_in[25];

    bf16 *XTh, *XTl, *fTh, *fTl, *qTh, *qTl, *kTh, *kTl, *vh, *vl;
    bf16 *Ph, *Pl, *resh, *resl;
    bf16 *rWh, *rWl, *qWh, *qWl, *kWh, *kWl, *vWh, *vWl, *uWh, *uWl;
    float* logits;
    cudaGetSymbolAddress((void**)&XTh, g_XTh); cudaGetSymbolAddress((void**)&XTl, g_XTl);
    cudaGetSymbolAddress((void**)&fTh, g_fTh); cudaGetSymbolAddress((void**)&fTl, g_fTl);
    cudaGetSymbolAddress((void**)&qTh, g_qTh); cudaGetSymbolAddress((void**)&qTl, g_qTl);
    cudaGetSymbolAddress((void**)&kTh, g_kTh); cudaGetSymbolAddress((void**)&kTl, g_kTl);
    cudaGetSymbolAddress((void**)&vh,  g_vh);  cudaGetSymbolAddress((void**)&vl,  g_vl);
    cudaGetSymbolAddress((void**)&Ph,  g_Ph);  cudaGetSymbolAddress((void**)&Pl,  g_Pl);
    cudaGetSymbolAddress((void**)&resh, g_resh); cudaGetSymbolAddress((void**)&resl, g_resl);
    cudaGetSymbolAddress((void**)&logits, g_logits);
    cudaGetSymbolAddress((void**)&rWh, g_rWh); cudaGetSymbolAddress((void**)&rWl, g_rWl);
    cudaGetSymbolAddress((void**)&qWh, g_qWh); cudaGetSymbolAddress((void**)&qWl, g_qWl);
    cudaGetSymbolAddress((void**)&kWh, g_kWh); cudaGetSymbolAddress((void**)&kWl, g_kWl);
    cudaGetSymbolAddress((void**)&vWh, g_vWh); cudaGetSymbolAddress((void**)&vWl, g_vWl);
    cudaGetSymbolAddress((void**)&uWh, g_uWh); cudaGetSymbolAddress((void**)&uWl, g_uWl);

    cudaFuncSetAttribute(mma_gemm<EPI_BNCOL_SPLIT>, cudaFuncAttributeMaxDynamicSharedMemorySize, SMEM_TOTAL);
    cudaFuncSetAttribute(mma_gemm<EPI_BNROW_SPLIT>, cudaFuncAttributeMaxDynamicSharedMemorySize, SMEM_TOTAL);
    cudaFuncSetAttribute(mma_gemm<EPI_F32>,         cudaFuncAttributeMaxDynamicSharedMemorySize, SMEM_TOTAL);
    cudaFuncSetAttribute(mma_gemm<EPI_RESID_SPLIT>, cudaFuncAttributeMaxDynamicSharedMemorySize, SMEM_TOTAL);
    cudaFuncSetAttribute(mma_gemm<EPI_BNROW_F32>,   cudaFuncAttributeMaxDynamicSharedMemorySize, SMEM_TOTAL);

    // ---- prep ----
    split_w_kernel<<<(RDIM * CDIM + 255) / 256, 256>>>(rW, rWh, rWl, RDIM * CDIM);
    split_w_kernel<<<(RDIM * RDIM + 255) / 256, 256>>>(qW, qWh, qWl, RDIM * RDIM);
    split_w_kernel<<<(RDIM * RDIM + 255) / 256, 256>>>(kW, kWh, kWl, RDIM * RDIM);
    split_w_kernel<<<(RDIM * RDIM + 255) / 256, 256>>>(vW, vWh, vWl, RDIM * RDIM);
    split_w_kernel<<<(CDIM * RDIM + 255) / 256, 256>>>(uW, uWh, uWl, CDIM * RDIM);
    transpose_split_kernel<<<dim3(CDIM / 32, NDIM / 32, BATCH), dim3(32, 8)>>>(feature, XTh, XTl);

    const size_t nrB = (size_t)NDIM * RDIM;
    const size_t ncB = (size_t)NDIM * CDIM;
    const size_t rnB = (size_t)RDIM * NDIM;
    const size_t nnB = (size_t)NDIM * NDIM;

    // 1) fT[n,r] = BN_ReLU( sum_c XT[n,c]*rW[r,c] )
    mma_gemm<EPI_BNCOL_SPLIT><<<dim3(RDIM / 128, NDIM / 128, BATCH), 256, SMEM_TOTAL>>>(
        CDIM, XTh, XTl, CDIM, ncB, rWh, rWl, CDIM, 0,
        fTh, fTl, RDIM, nrB, rg, rb, rm, rv, nullptr, nullptr, 0, 0);

    // 2) qT, kT
    mma_gemm<EPI_BNCOL_SPLIT><<<dim3(RDIM / 128, NDIM / 128, BATCH), 256, SMEM_TOTAL>>>(
        RDIM, fTh, fTl, RDIM, nrB, qWh, qWl, RDIM, 0,
        qTh, qTl, RDIM, nrB, qg, qb, qm, qv, nullptr, nullptr, 0, 0);
    mma_gemm<EPI_BNCOL_SPLIT><<<dim3(RDIM / 128, NDIM / 128, BATCH), 256, SMEM_TOTAL>>>(
        RDIM, fTh, fTl, RDIM, nrB, kWh, kWl, RDIM, 0,
        kTh, kTl, RDIM, nrB, kg, kb, km, kv, nullptr, nullptr, 0, 0);

    // 3) v[r,m] = BN_ReLU over rows r
    mma_gemm<EPI_BNROW_SPLIT><<<dim3(NDIM / 128, RDIM / 128, BATCH), 256, SMEM_TOTAL>>>(
        RDIM, vWh, vWl, RDIM, 0, fTh, fTl, RDIM, nrB,
        vh, vl, NDIM, rnB, vg, vb, vm, vv, nullptr, nullptr, 0, 0);

    // 4) logits[n,m] = sum_c qT[n,c]*kT[m,c]
    mma_gemm<EPI_F32><<<dim3(NDIM / 128, NDIM / 128, BATCH), 256, SMEM_TOTAL>>>(
        RDIM, qTh, qTl, RDIM, nrB, kTh, kTl, RDIM, nrB,
        logits, nullptr, NDIM, nnB, nullptr, nullptr, nullptr, nullptr,
        nullptr, nullptr, 0, 0);

    // 5) softmax -> P hi/lo
    softmax_split_kernel<<<BATCH * NDIM, 256>>>(logits, Ph, Pl);

    // 6) resid[n,r] = fT[n,r] + sum_m P[n,m]*v[r,m]
    mma_gemm<EPI_RESID_SPLIT><<<dim3(RDIM / 128, NDIM / 128, BATCH), 256, SMEM_TOTAL>>>(
        NDIM, Ph, Pl, NDIM, nnB, vh, vl, NDIM, rnB,
        resh, resl, RDIM, nrB, nullptr, nullptr, nullptr, nullptr,
        fTh, fTl, RDIM, nrB);

    // 7) out[C,n] = BN_ReLU( sum_r uW[C,r]*resid[n,r] )
    mma_gemm<EPI_BNROW_F32><<<dim3(NDIM / 128, CDIM / 128, BATCH), 256, SMEM_TOTAL>>>(
        RDIM, uWh, uWl, RDIM, 0, resh, resl, RDIM, nrB,
        (float*)d_out, nullptr, NDIM, (size_t)CDIM * NDIM,
        ug, ub, um, uv, nullptr, nullptr, 0, 0);
}

// round 4
// speedup vs baseline: 3.2764x; 1.4500x over previous
#include <cuda_runtime.h>
#include <cuda.h>
#include <cuda_bf16.h>
#include <stdint.h>
#include <math.h>

#define BATCH 4
#define CDIM  2048
#define RDIM  512
#define NDIM  4096
#define EPSBN 1e-5f

typedef __nv_bfloat16 bf16;

// ===========================================================================
// Scratch (device globals; no allocation allowed)
// ===========================================================================
__device__ bf16 g_XTh[(size_t)BATCH * NDIM * CDIM];   // feature^T hi  [B][N][C]
__device__ bf16 g_XTl[(size_t)BATCH * NDIM * CDIM];
__device__ bf16 g_fTh[(size_t)BATCH * NDIM * RDIM];   // f^T [B][N][R]
__device__ bf16 g_fTl[(size_t)BATCH * NDIM * RDIM];
__device__ bf16 g_qTh[(size_t)BATCH * NDIM * RDIM];
__device__ bf16 g_qTl[(size_t)BATCH * NDIM * RDIM];
__device__ bf16 g_kTh[(size_t)BATCH * NDIM * RDIM];
__device__ bf16 g_kTl[(size_t)BATCH * NDIM * RDIM];
__device__ bf16 g_vh [(size_t)BATCH * RDIM * NDIM];   // v [B][R][N]
__device__ bf16 g_vl [(size_t)BATCH * RDIM * NDIM];
__device__ float g_logits[(size_t)BATCH * NDIM * NDIM];
__device__ bf16 g_Ph [(size_t)BATCH * NDIM * NDIM];
__device__ bf16 g_Pl [(size_t)BATCH * NDIM * NDIM];
__device__ bf16 g_resh[(size_t)BATCH * NDIM * RDIM];  // (f+upd)^T [B][N][R]
__device__ bf16 g_resl[(size_t)BATCH * NDIM * RDIM];
__device__ bf16 g_rWh[RDIM * CDIM], g_rWl[RDIM * CDIM];
__device__ bf16 g_qWh[RDIM * RDIM], g_qWl[RDIM * RDIM];
__device__ bf16 g_kWh[RDIM * RDIM], g_kWl[RDIM * RDIM];
__device__ bf16 g_vWh[RDIM * RDIM], g_vWl[RDIM * RDIM];
__device__ bf16 g_uWh[CDIM * RDIM], g_uWl[CDIM * RDIM];

// ===========================================================================
// PTX helpers (sm_90-level only: ldmatrix, mma.sync, TMA bulk tensor, mbarrier)
// ===========================================================================
__device__ __forceinline__ uint32_t smem_u32(const void* p) {
    uint32_t a;
    asm("{ .reg .u64 t; cvta.to.shared.u64 t, %1; cvt.u32.u64 %0, t; }" : "=r"(a) : "l"(p));
    return a;
}
__device__ __forceinline__ void ldm_x4(uint32_t* r, uint32_t addr) {
    asm volatile("ldmatrix.sync.aligned.m8n8.x4.shared.b16 {%0,%1,%2,%3}, [%4];"
                 : "=r"(r[0]), "=r"(r[1]), "=r"(r[2]), "=r"(r[3]) : "r"(addr));
}
__device__ __forceinline__ void mma_bf16(float* d, const uint32_t* a, const uint32_t* b) {
    asm volatile("mma.sync.aligned.m16n8k16.row.col.f32.bf16.bf16.f32 "
                 "{%0,%1,%2,%3}, {%4,%5,%6,%7}, {%8,%9}, {%0,%1,%2,%3};"
                 : "+f"(d[0]), "+f"(d[1]), "+f"(d[2]), "+f"(d[3])
                 : "r"(a[0]), "r"(a[1]), "r"(a[2]), "r"(a[3]), "r"(b[0]), "r"(b[1]));
}
#define MBARRIER_INIT(addr, cnt) \
    asm volatile("mbarrier.init.shared.b64 [%0], %1;" :: "r"((uint32_t)(addr)), "r"((uint32_t)(cnt)) : "memory")
#define MBARRIER_EXPECT_TX(addr, bytes) \
    asm volatile("mbarrier.arrive.expect_tx.shared.b64 _, [%0], %1;" \
                 :: "r"((uint32_t)(addr)), "r"((uint32_t)(bytes)) : "memory")
#define MBARRIER_WAIT_PARITY(mbar, parity) do { \
    uint32_t _m = (uint32_t)(mbar); uint32_t _p = (uint32_t)(parity); uint32_t _d; \
    asm volatile("{\n\t.reg .pred p;\n\t" \
        "mbarrier.try_wait.parity.shared.b64 p, [%1], %2;\n\t" \
        "selp.b32 %0, 1, 0, p;\n\t}" : "=r"(_d) : "r"(_m), "r"(_p) : "memory"); \
    if (!_d) { \
        asm volatile("{\n\t.reg .pred P1;\n\t" \
            "WL_%=:\n\t" \
            "mbarrier.try_wait.parity.shared.b64 P1, [%0], %1;\n\t" \
            "@P1 bra.uni WD_%=;\n\t" \
            "bra.uni WL_%=;\n\t" \
            "WD_%=:\n\t}" :: "r"(_m), "r"(_p) : "memory"); \
    } \
} while (0)
#define TMA_LOAD_2D(saddr, map_ptr, cx, cy, mbar) \
    asm volatile("cp.async.bulk.tensor.2d.shared::cluster.global.tile.mbarrier::complete_tx::bytes " \
        "[%0], [%1, {%2, %3}], [%4];" \
        :: "r"((uint32_t)(saddr)), "l"(map_ptr), "r"((int)(cx)), "r"((int)(cy)), \
           "r"((uint32_t)(mbar)) : "memory")
#define SWZ128(off) ((off) ^ (((off) >> 3) & 0x70))

// ===========================================================================
// Prep kernels
// ===========================================================================
__global__ void split_w_kernel(const float* __restrict__ w, bf16* __restrict__ h,
                               bf16* __restrict__ l, int n) {
    int i = blockIdx.x * 256 + threadIdx.x;
    if (i < n) {
        float x = w[i];
        bf16 hi = __float2bfloat16(x);
        h[i] = hi;
        l[i] = __float2bfloat16(x - __bfloat162float(hi));
    }
}

// feature [B][C][N] fp32 -> XT [B][N][C] split bf16
__global__ __launch_bounds__(256) void transpose_split_kernel(
    const float* __restrict__ src, bf16* __restrict__ dh, bf16* __restrict__ dl) {
    __shared__ float t[32][33];
    const int bz = blockIdx.z;
    const float* s = src + (size_t)bz * CDIM * NDIM;
    const size_t dbase = (size_t)bz * NDIM * CDIM;
    const int c0 = blockIdx.x * 32, n0 = blockIdx.y * 32;
    const int tx = threadIdx.x, ty = threadIdx.y;  // 32 x 8
    #pragma unroll
    for (int i = 0; i < 4; i++)
        t[ty + 8 * i][tx] = s[(size_t)(c0 + ty + 8 * i) * NDIM + n0 + tx];
    __syncthreads();
    #pragma unroll
    for (int i = 0; i < 4; i++) {
        const int n = n0 + ty + 8 * i, c = c0 + tx;
        const float x = t[tx][ty + 8 * i];
        bf16 h = __float2bfloat16(x);
        dh[dbase + (size_t)n * CDIM + c] = h;
        dl[dbase + (size_t)n * CDIM + c] = __float2bfloat16(x - __bfloat162float(h));
    }
}

// ===========================================================================
// Split-bf16 mma.sync GEMM with TMA operand loads.
// D[m,n] = sum_k A[m,k]*B[n,k] (both K-major). CTA tile 128x128, BK=64,
// 3-stage mbarrier pipeline, SW128-swizzled SMEM tiles, 256 thr / 8 warps.
// ===========================================================================
enum { EPI_BNCOL_SPLIT = 0, EPI_BNROW_SPLIT = 1, EPI_F32 = 2,
       EPI_RESID_SPLIT = 3, EPI_BNROW_F32 = 4 };

#define TILE_SZ   16384            // 128 rows x 128 B
#define STAGE_SZ  (4 * TILE_SZ)    // Ah, Al, Bh, Bl
#define SMEM_HDR  2048
#define NSTAGE    3
#define SMEM_TOTAL (SMEM_HDR + NSTAGE * STAGE_SZ)   // 198656

template<int EPI>
__global__ __launch_bounds__(256, 1) void mma_gemm(
    int iters, int rowsA_pb, int rowsB_pb,
    const __grid_constant__ CUtensorMap mAh,
    const __grid_constant__ CUtensorMap mAl,
    const __grid_constant__ CUtensorMap mBh,
    const __grid_constant__ CUtensorMap mBl,
    void* __restrict__ O1, void* __restrict__ O2, long ldc, size_t cB,
    const float* __restrict__ bn_g, const float* __restrict__ bn_b,
    const float* __restrict__ bn_m, const float* __restrict__ bn_v,
    const bf16* __restrict__ Rh, const bf16* __restrict__ Rl, long ldr, size_t rB)
{
    extern __shared__ __align__(1024) char smem[];
    const uint32_t sb = smem_u32(smem);
    const int tid  = threadIdx.x;
    const int wid  = tid >> 5;
    const int lane = tid & 31;
    const int bm = blockIdx.y * 128;
    const int bn = blockIdx.x * 128;
    const int bz = blockIdx.z;
    const int yA = bz * rowsA_pb + bm;
    const int yB = bz * rowsB_pb + bn;

    float* sinv  = (float*)(smem + 256);
    float* sbeta = (float*)(smem + 768);
    if ((EPI == EPI_BNCOL_SPLIT || EPI == EPI_BNROW_SPLIT || EPI == EPI_BNROW_F32)
        && tid < 128) {
        const int idx = (EPI == EPI_BNCOL_SPLIT) ? (bn + tid) : (bm + tid);
        const float iv = bn_g[idx] * rsqrtf(bn_v[idx] + EPSBN);
        sinv[tid]  = iv;
        sbeta[tid] = bn_b[idx] - bn_m[idx] * iv;
    }
    if (tid == 0) {
        MBARRIER_INIT(sb + 0, 1);
        MBARRIER_INIT(sb + 8, 1);
        MBARRIER_INIT(sb + 16, 1);
    }
    __syncthreads();

    // producer: issue stage s into buffer s%3
    auto issue = [&](int s) {
        const int buf = s % NSTAGE;
        const uint32_t tb = sb + SMEM_HDR + buf * STAGE_SZ;
        const uint32_t mb = sb + buf * 8;
        MBARRIER_EXPECT_TX(mb, STAGE_SZ);
        const int kx = s * 64;
        TMA_LOAD_2D(tb,               &mAh, kx, yA, mb);
        TMA_LOAD_2D(tb + TILE_SZ,     &mAl, kx, yA, mb);
        TMA_LOAD_2D(tb + 2 * TILE_SZ, &mBh, kx, yB, mb);
        TMA_LOAD_2D(tb + 3 * TILE_SZ, &mBl, kx, yB, mb);
    };
    if (tid == 0) {
        issue(0); issue(1);
        if (iters > 2) issue(2);
    }

    float acc[2][8][4];
    #pragma unroll
    for (int mi = 0; mi < 2; mi++)
        #pragma unroll
        for (int ni = 0; ni < 8; ni++)
            #pragma unroll
            for (int j = 0; j < 4; j++) acc[mi][ni][j] = 0.0f;

    const int warp_m = wid & 3;      // 4 warps along m (32 rows each)
    const int warp_n = wid >> 2;     // 2 warps along n (64 cols each)

    // per-lane base offsets (pre-swizzle) inside a 128x128B tile
    const uint32_t aRowOff = (uint32_t)(warp_m * 32 + (lane & 15)) * 128 + (lane >> 4) * 16;
    const uint32_t bRowOff = (uint32_t)(warp_n * 64 + (lane & 7) + ((lane & 16) >> 1)) * 128
                             + (lane & 8) * 2;

    for (int it = 0; it < iters; ++it) {
        const int buf = it % NSTAGE;
        const int ph  = (it / NSTAGE) & 1;
        MBARRIER_WAIT_PARITY(sb + buf * 8, ph);

        const uint32_t tb = sb + SMEM_HDR + buf * STAGE_SZ;
        #pragma unroll
        for (int ks = 0; ks < 4; ks++) {
            uint32_t ah[2][4], al[2][4], bh[8][2], bl[8][2];
            #pragma unroll
            for (int mi = 0; mi < 2; mi++) {
                const uint32_t off = aRowOff + mi * (16 * 128) + ks * 32;
                ldm_x4(ah[mi], tb + SWZ128(off));
                ldm_x4(al[mi], tb + TILE_SZ + SWZ128(off));
            }
            #pragma unroll
            for (int nf = 0; nf < 4; nf++) {
                const uint32_t off = bRowOff + nf * (16 * 128) + ks * 32;
                uint32_t r[4];
                ldm_x4(r, tb + 2 * TILE_SZ + SWZ128(off));
                bh[2 * nf][0] = r[0]; bh[2 * nf][1] = r[1];
                bh[2 * nf + 1][0] = r[2]; bh[2 * nf + 1][1] = r[3];
                ldm_x4(r, tb + 3 * TILE_SZ + SWZ128(off));
                bl[2 * nf][0] = r[0]; bl[2 * nf][1] = r[1];
                bl[2 * nf + 1][0] = r[2]; bl[2 * nf + 1][1] = r[3];
            }
            #pragma unroll
            for (int mi = 0; mi < 2; mi++)
                #pragma unroll
                for (int ni = 0; ni < 8; ni++) {
                    mma_bf16(acc[mi][ni], ah[mi], bh[ni]);
                    mma_bf16(acc[mi][ni], ah[mi], bl[ni]);
                    mma_bf16(acc[mi][ni], al[mi], bh[ni]);
                }
        }
        __syncthreads();
        if (tid == 0 && it + NSTAGE < iters) issue(it + NSTAGE);
    }

    // ---------------- epilogue (register accumulators) ----------------
    const int r_lo = lane >> 2;          // 0..7
    const int c_lo = (lane & 3) * 2;     // 0,2,4,6
    #pragma unroll
    for (int mi = 0; mi < 2; mi++) {
        #pragma unroll
        for (int half = 0; half < 2; half++) {
            const int lrow = warp_m * 32 + mi * 16 + r_lo + half * 8;
            const int grow = bm + lrow;
            #pragma unroll
            for (int ni = 0; ni < 8; ni++) {
                const int lcol = warp_n * 64 + ni * 8 + c_lo;
                const int gcol = bn + lcol;
                float v0 = acc[mi][ni][half * 2 + 0];
                float v1 = acc[mi][ni][half * 2 + 1];

                if (EPI == EPI_BNCOL_SPLIT) {
                    v0 = fmaxf(v0 * sinv[lcol]     + sbeta[lcol],     0.0f);
                    v1 = fmaxf(v1 * sinv[lcol + 1] + sbeta[lcol + 1], 0.0f);
                } else if (EPI == EPI_BNROW_SPLIT || EPI == EPI_BNROW_F32) {
                    v0 = fmaxf(v0 * sinv[lrow] + sbeta[lrow], 0.0f);
                    v1 = fmaxf(v1 * sinv[lrow] + sbeta[lrow], 0.0f);
                } else if (EPI == EPI_RESID_SPLIT) {
                    const size_t ro = (size_t)bz * rB + (size_t)grow * ldr + gcol;
                    const __nv_bfloat162 rh = *(const __nv_bfloat162*)(Rh + ro);
                    const __nv_bfloat162 rl = *(const __nv_bfloat162*)(Rl + ro);
                    v0 += __bfloat162float(rh.x) + __bfloat162float(rl.x);
                    v1 += __bfloat162float(rh.y) + __bfloat162float(rl.y);
                }

                if (EPI == EPI_F32 || EPI == EPI_BNROW_F32) {
                    float* po = (float*)O1 + (size_t)bz * cB + (size_t)grow * ldc + gcol;
                    po[0] = v0; po[1] = v1;
                } else {
                    const size_t oo = (size_t)bz * cB + (size_t)grow * ldc + gcol;
                    bf16 h0 = __float2bfloat16(v0);
                    bf16 h1 = __float2bfloat16(v1);
                    __nv_bfloat162 hv; hv.x = h0; hv.y = h1;
                    __nv_bfloat162 lv;
                    lv.x = __float2bfloat16(v0 - __bfloat162float(h0));
                    lv.y = __float2bfloat16(v1 - __bfloat162float(h1));
                    *(__nv_bfloat162*)((bf16*)O1 + oo) = hv;
                    *(__nv_bfloat162*)((bf16*)O2 + oo) = lv;
                }
            }
        }
    }
}

// ===========================================================================
// Row softmax over fp32 logits -> split bf16 P
// ===========================================================================
__global__ __launch_bounds__(256) void softmax_split_kernel(
    const float* __restrict__ logits, bf16* __restrict__ ph, bf16* __restrict__ pl)
{
    const float* row = logits + (size_t)blockIdx.x * NDIM;
    __nv_bfloat162* ph2 = (__nv_bfloat162*)(ph + (size_t)blockIdx.x * NDIM);
    __nv_bfloat162* pl2 = (__nv_bfloat162*)(pl + (size_t)blockIdx.x * NDIM);
    const int t = threadIdx.x;

    float4 v[4];
    float mx = -3.4e38f;
    #pragma unroll
    for (int i = 0; i < 4; i++) {
        v[i] = reinterpret_cast<const float4*>(row)[i * 256 + t];
        mx = fmaxf(mx, fmaxf(fmaxf(v[i].x, v[i].y), fmaxf(v[i].z, v[i].w)));
    }
    __shared__ float red_m[8], red_s[8];
    #pragma unroll
    for (int o = 16; o > 0; o >>= 1) mx = fmaxf(mx, __shfl_xor_sync(0xffffffffu, mx, o));
    if ((t & 31) == 0) red_m[t >> 5] = mx;
    __syncthreads();
    mx = fmaxf(fmaxf(fmaxf(red_m[0], red_m[1]), fmaxf(red_m[2], red_m[3])),
               fmaxf(fmaxf(red_m[4], red_m[5]), fmaxf(red_m[6], red_m[7])));
    float sum = 0.0f;
    #pragma unroll
    for (int i = 0; i < 4; i++) {
        v[i].x = expf(v[i].x - mx); sum += v[i].x;
        v[i].y = expf(v[i].y - mx); sum += v[i].y;
        v[i].z = expf(v[i].z - mx); sum += v[i].z;
        v[i].w = expf(v[i].w - mx); sum += v[i].w;
    }
    #pragma unroll
    for (int o = 16; o > 0; o >>= 1) sum += __shfl_xor_sync(0xffffffffu, sum, o);
    if ((t & 31) == 0) red_s[t >> 5] = sum;
    __syncthreads();
    sum = (red_s[0] + red_s[1]) + (red_s[2] + red_s[3])
        + (red_s[4] + red_s[5]) + (red_s[6] + red_s[7]);
    const float r = 1.0f / sum;
    #pragma unroll
    for (int i = 0; i < 4; i++) {
        float a = v[i].x * r, b = v[i].y * r, c = v[i].z * r, d = v[i].w * r;
        bf16 ha = __float2bfloat16(a), hb = __float2bfloat16(b);
        bf16 hc = __float2bfloat16(c), hd = __float2bfloat16(d);
        __nv_bfloat162 h0; h0.x = ha; h0.y = hb;
        __nv_bfloat162 h1; h1.x = hc; h1.y = hd;
        ph2[(i * 256 + t) * 2 + 0] = h0;
        ph2[(i * 256 + t) * 2 + 1] = h1;
        __nv_bfloat162 l0, l1;
        l0.x = __float2bfloat16(a - __bfloat162float(ha));
        l0.y = __float2bfloat16(b - __bfloat162float(hb));
        l1.x = __float2bfloat16(c - __bfloat162float(hc));
        l1.y = __float2bfloat16(d - __bfloat162float(hd));
        pl2[(i * 256 + t) * 2 + 0] = l0;
        pl2[(i * 256 + t) * 2 + 1] = l1;
    }
}

// ===========================================================================
// Host: tensor-map encoding via runtime-resolved driver entry point
// ===========================================================================
typedef CUresult (*EncodeFn)(
    CUtensorMap*, CUtensorMapDataType, cuuint32_t, void*,
    const cuuint64_t*, const cuuint64_t*, const cuuint32_t*, const cuuint32_t*,
    CUtensorMapInterleave, CUtensorMapSwizzle, CUtensorMapL2promotion,
    CUtensorMapFloatOOBfill);

static EncodeFn get_encoder() {
    static EncodeFn fn = nullptr;
    if (!fn) {
        void* p = nullptr;
        cudaDriverEntryPointQueryResult st;
        cudaGetDriverEntryPointByVersion("cuTensorMapEncodeTiled", &p, 12000,
                                         cudaEnableDefault, &st);
        fn = (EncodeFn)p;
    }
    return fn;
}

// K-major bf16 2D map: rows x cols, row stride ld (elements), box 64x128, SW128
static void enc_map(CUtensorMap* m, void* ptr, uint64_t rows, uint64_t cols, uint64_t ld) {
    cuuint64_t dims[2]    = {cols, rows};
    cuuint64_t strides[1] = {ld * 2};
    cuuint32_t box[2]     = {64, 128};
    cuuint32_t es[2]      = {1, 1};
    get_encoder()(m, CU_TENSOR_MAP_DATA_TYPE_BFLOAT16, 2, ptr, dims, strides, box, es,
                  CU_TENSOR_MAP_INTERLEAVE_NONE, CU_TENSOR_MAP_SWIZZLE_128B,
                  CU_TENSOR_MAP_L2_PROMOTION_L2_128B, CU_TENSOR_MAP_FLOAT_OOB_FILL_NONE);
}

// ===========================================================================
extern "C" void kernel_launch(void* const* d_in, const int* in_sizes, int n_in,
                              void* d_out, int out_size)
{
    (void)in_sizes; (void)n_in; (void)out_size;
    const float* feature = (const float*)d_in[0];
    const float* rW = (const float*)d_in[1];
    const float* rg = (const float*)d_in[2];  const float* rb = (const float*)d_in[3];
    const float* rm = (const float*)d_in[4];  const float* rv = (const float*)d_in[5];
    const float* qW = (const float*)d_in[6];
    const float* qg = (const float*)d_in[7];  const float* qb = (const float*)d_in[8];
    const float* qm = (const float*)d_in[9];  const float* qv = (const float*)d_in[10];
    const float* kW = (const float*)d_in[11];
    const float* kg = (const float*)d_in[12]; const float* kb = (const float*)d_in[13];
    const float* km = (const float*)d_in[14]; const float* kv = (const float*)d_in[15];
    const float* vW = (const float*)d_in[16];
    const float* vg = (const float*)d_in[17]; const float* vb = (const float*)d_in[18];
    const float* vm = (const float*)d_in[19]; const float* vv = (const float*)d_in[20];
    const float* uW = (const float*)d_in[21];
    const float* ug = (const float*)d_in[22]; const float* ub = (const float*)d_in[23];
    const float* um = (const float*)d_in[24]; const float* uv = (const float*)d_in[25];

    bf16 *XTh, *XTl, *fTh, *fTl, *qTh, *qTl, *kTh, *kTl, *vh, *vl;
    bf16 *Ph, *Pl, *resh, *resl;
    bf16 *rWh, *rWl, *qWh, *qWl, *kWh, *kWl, *vWh, *vWl, *uWh, *uWl;
    float* logits;
    cudaGetSymbolAddress((void**)&XTh, g_XTh); cudaGetSymbolAddress((void**)&XTl, g_XTl);
    cudaGetSymbolAddress((void**)&fTh, g_fTh); cudaGetSymbolAddress((void**)&fTl, g_fTl);
    cudaGetSymbolAddress((void**)&qTh, g_qTh); cudaGetSymbolAddress((void**)&qTl, g_qTl);
    cudaGetSymbolAddress((void**)&kTh, g_kTh); cudaGetSymbolAddress((void**)&kTl, g_kTl);
    cudaGetSymbolAddress((void**)&vh,  g_vh);  cudaGetSymbolAddress((void**)&vl,  g_vl);
    cudaGetSymbolAddress((void**)&Ph,  g_Ph);  cudaGetSymbolAddress((void**)&Pl,  g_Pl);
    cudaGetSymbolAddress((void**)&resh, g_resh); cudaGetSymbolAddress((void**)&resl, g_resl);
    cudaGetSymbolAddress((void**)&logits, g_logits);
    cudaGetSymbolAddress((void**)&rWh, g_rWh); cudaGetSymbolAddress((void**)&rWl, g_rWl);
    cudaGetSymbolAddress((void**)&qWh, g_qWh); cudaGetSymbolAddress((void**)&qWl, g_qWl);
    cudaGetSymbolAddress((void**)&kWh, g_kWh); cudaGetSymbolAddress((void**)&kWl, g_kWl);
    cudaGetSymbolAddress((void**)&vWh, g_vWh); cudaGetSymbolAddress((void**)&vWl, g_vWl);
    cudaGetSymbolAddress((void**)&uWh, g_uWh); cudaGetSymbolAddress((void**)&uWl, g_uWl);

    cudaFuncSetAttribute(mma_gemm<EPI_BNCOL_SPLIT>, cudaFuncAttributeMaxDynamicSharedMemorySize, SMEM_TOTAL);
    cudaFuncSetAttribute(mma_gemm<EPI_BNROW_SPLIT>, cudaFuncAttributeMaxDynamicSharedMemorySize, SMEM_TOTAL);
    cudaFuncSetAttribute(mma_gemm<EPI_F32>,         cudaFuncAttributeMaxDynamicSharedMemorySize, SMEM_TOTAL);
    cudaFuncSetAttribute(mma_gemm<EPI_RESID_SPLIT>, cudaFuncAttributeMaxDynamicSharedMemorySize, SMEM_TOTAL);
    cudaFuncSetAttribute(mma_gemm<EPI_BNROW_F32>,   cudaFuncAttributeMaxDynamicSharedMemorySize, SMEM_TOTAL);

    // ---- tensor maps (encoded at capture time, snapshotted as kernel params) ----
    const uint64_t BN = (uint64_t)BATCH * NDIM;
    const uint64_t BR = (uint64_t)BATCH * RDIM;
    CUtensorMap tXTh, tXTl, tfTh, tfTl, tqTh, tqTl, tkTh, tkTl, tvh, tvl;
    CUtensorMap tPh, tPl, tresh, tresl;
    CUtensorMap trWh, trWl, tqWh, tqWl, tkWh, tkWl, tvWh, tvWl, tuWh, tuWl;
    enc_map(&tXTh, XTh, BN, CDIM, CDIM);  enc_map(&tXTl, XTl, BN, CDIM, CDIM);
    enc_map(&tfTh, fTh, BN, RDIM, RDIM);  enc_map(&tfTl, fTl, BN, RDIM, RDIM);
    enc_map(&tqTh, qTh, BN, RDIM, RDIM);  enc_map(&tqTl, qTl, BN, RDIM, RDIM);
    enc_map(&tkTh, kTh, BN, RDIM, RDIM);  enc_map(&tkTl, kTl, BN, RDIM, RDIM);
    enc_map(&tvh,  vh,  BR, NDIM, NDIM);  enc_map(&tvl,  vl,  BR, NDIM, NDIM);
    enc_map(&tPh,  Ph,  BN, NDIM, NDIM);  enc_map(&tPl,  Pl,  BN, NDIM, NDIM);
    enc_map(&tresh, resh, BN, RDIM, RDIM); enc_map(&tresl, resl, BN, RDIM, RDIM);
    enc_map(&trWh, rWh, RDIM, CDIM, CDIM); enc_map(&trWl, rWl, RDIM, CDIM, CDIM);
    enc_map(&tqWh, qWh, RDIM, RDIM, RDIM); enc_map(&tqWl, qWl, RDIM, RDIM, RDIM);
    enc_map(&tkWh, kWh, RDIM, RDIM, RDIM); enc_map(&tkWl, kWl, RDIM, RDIM, RDIM);
    enc_map(&tvWh, vWh, RDIM, RDIM, RDIM); enc_map(&tvWl, vWl, RDIM, RDIM, RDIM);
    enc_map(&tuWh, uWh, CDIM, RDIM, RDIM); enc_map(&tuWl, uWl, CDIM, RDIM, RDIM);

    // ---- prep ----
    split_w_kernel<<<(RDIM * CDIM + 255) / 256, 256>>>(rW, rWh, rWl, RDIM * CDIM);
    split_w_kernel<<<(RDIM * RDIM + 255) / 256, 256>>>(qW, qWh, qWl, RDIM * RDIM);
    split_w_kernel<<<(RDIM * RDIM + 255) / 256, 256>>>(kW, kWh, kWl, RDIM * RDIM);
    split_w_kernel<<<(RDIM * RDIM + 255) / 256, 256>>>(vW, vWh, vWl, RDIM * RDIM);
    split_w_kernel<<<(CDIM * RDIM + 255) / 256, 256>>>(uW, uWh, uWl, CDIM * RDIM);
    transpose_split_kernel<<<dim3(CDIM / 32, NDIM / 32, BATCH), dim3(32, 8)>>>(feature, XTh, XTl);

    const size_t nrB = (size_t)NDIM * RDIM;
    const size_t rnB = (size_t)RDIM * NDIM;
    const size_t nnB = (size_t)NDIM * NDIM;

    // 1) fT[n,r] = BN_ReLU( sum_c XT[n,c]*rW[r,c] ), K=2048 -> 32 iters
    mma_gemm<EPI_BNCOL_SPLIT><<<dim3(RDIM / 128, NDIM / 128, BATCH), 256, SMEM_TOTAL>>>(
        32, NDIM, 0, tXTh, tXTl, trWh, trWl,
        fTh, fTl, RDIM, nrB, rg, rb, rm, rv, nullptr, nullptr, 0, 0);

    // 2) qT, kT  (K=512 -> 8 iters)
    mma_gemm<EPI_BNCOL_SPLIT><<<dim3(RDIM / 128, NDIM / 128, BATCH), 256, SMEM_TOTAL>>>(
        8, NDIM, 0, tfTh, tfTl, tqWh, tqWl,
        qTh, qTl, RDIM, nrB, qg, qb, qm, qv, nullptr, nullptr, 0, 0);
    mma_gemm<EPI_BNCOL_SPLIT><<<dim3(RDIM / 128, NDIM / 128, BATCH), 256, SMEM_TOTAL>>>(
        8, NDIM, 0, tfTh, tfTl, tkWh, tkWl,
        kTh, kTl, RDIM, nrB, kg, kb, km, kv, nullptr, nullptr, 0, 0);

    // 3) v[r,m] = BN_ReLU over rows r  (A=vW, B=fT)
    mma_gemm<EPI_BNROW_SPLIT><<<dim3(NDIM / 128, RDIM / 128, BATCH), 256, SMEM_TOTAL>>>(
        8, 0, NDIM, tvWh, tvWl, tfTh, tfTl,
        vh, vl, NDIM, rnB, vg, vb, vm, vv, nullptr, nullptr, 0, 0);

    // 4) logits[n,m] = sum_c qT[n,c]*kT[m,c]
    mma_gemm<EPI_F32><<<dim3(NDIM / 128, NDIM / 128, BATCH), 256, SMEM_TOTAL>>>(
        8, NDIM, NDIM, tqTh, tqTl, tkTh, tkTl,
        logits, nullptr, NDIM, nnB, nullptr, nullptr, nullptr, nullptr,
        nullptr, nullptr, 0, 0);

    // 5) softmax -> P hi/lo
    softmax_split_kernel<<<BATCH * NDIM, 256>>>(logits, Ph, Pl);

    // 6) resid[n,r] = fT[n,r] + sum_m P[n,m]*v[r,m]  (K=4096 -> 64 iters)
    mma_gemm<EPI_RESID_SPLIT><<<dim3(RDIM / 128, NDIM / 128, BATCH), 256, SMEM_TOTAL>>>(
        64, NDIM, RDIM, tPh, tPl, tvh, tvl,
        resh, resl, RDIM, nrB, nullptr, nullptr, nullptr, nullptr,
        fTh, fTl, RDIM, nrB);

    // 7) out[C,n] = BN_ReLU( sum_r uW[C,r]*resid[n,r] )
    mma_gemm<EPI_BNROW_F32><<<dim3(NDIM / 128, CDIM / 128, BATCH), 256, SMEM_TOTAL>>>(
        8, 0, NDIM, tuWh, tuWl, tresh, tresl,
        (float*)d_out, nullptr, NDIM, (size_t)CDIM * NDIM,
        ug, ub, um, uv, nullptr, nullptr, 0, 0);
}